// round 2
// baseline (speedup 1.0000x reference)
#include <cuda_runtime.h>
#include <stdint.h>

#define NN 32768      // B*M nodes
#define INDIM 256
#define HDIM 256      // H*D
#define NH 4
#define DD 64
#define BB 64
#define MM 512
#define EE 524288

// -------- device scratch (static; no allocations allowed) --------
static __device__ float g_q[NN * HDIM];
static __device__ float g_k[NN * HDIM];
static __device__ float g_v[NN * HDIM];
static __device__ float g_vmean[NN * DD];
static __device__ float g_pn[NN * NH * DD];     // q . kv (unnormalized numerator core), layout [n][h][d]
static __device__ float g_kv[BB * NH * DD * DD]; // per (b,h): [k][v] = sum_m k*v (unnormalized)
static __device__ float g_ksum[BB * NH * DD];
static __device__ float g_vsum[BB * NH * DD];
static __device__ float g_den[NN * NH];          // q . ksum (unnormalized)
static __device__ float g_deg[NN];
static __device__ float g_sumsq[2];              // [0]=sum q^2, [1]=sum k^2

// -------- init: zero accumulators --------
__global__ void init_kernel() {
    int i = blockIdx.x * 256 + threadIdx.x;
    if (i < NN) g_deg[i] = 0.f;
    if (i < 2) g_sumsq[i] = 0.f;
}

// -------- projection GEMM: C = A[N,256] @ W[256,256] + bias, fused sum-of-squares --------
// BM=128, BN=128, BK=8, 256 threads, 8x8 per-thread tile.
__global__ __launch_bounds__(256) void proj_kernel(
    const float* __restrict__ A, const float* __restrict__ W,
    const float* __restrict__ bias, int which, int sqidx)
{
    float* C = (which == 0) ? g_q : ((which == 1) ? g_k : g_v);
    __shared__ float As[8][128];   // [k][m]
    __shared__ float Ws[8][128];   // [k][n]
    int t = threadIdx.x;
    int row0 = blockIdx.y * 128;
    int col0 = blockIdx.x * 128;
    int la_r = t >> 1, la_c = (t & 1) * 4;     // A loader: 128 rows x 8 k
    int lw_r = t >> 5, lw_c = (t & 31) * 4;    // W loader: 8 rows x 128 n
    int rm0 = (t >> 4) * 8, rn0 = (t & 15) * 8;

    float acc[8][8];
#pragma unroll
    for (int i = 0; i < 8; i++)
#pragma unroll
        for (int j = 0; j < 8; j++) acc[i][j] = 0.f;

    for (int k0 = 0; k0 < 256; k0 += 8) {
        float4 a4 = *(const float4*)(A + (size_t)(row0 + la_r) * 256 + k0 + la_c);
        float4 w4 = *(const float4*)(W + (size_t)(k0 + lw_r) * 256 + col0 + lw_c);
        As[la_c + 0][la_r] = a4.x; As[la_c + 1][la_r] = a4.y;
        As[la_c + 2][la_r] = a4.z; As[la_c + 3][la_r] = a4.w;
        *(float4*)&Ws[lw_r][lw_c] = w4;
        __syncthreads();
#pragma unroll
        for (int kk = 0; kk < 8; kk++) {
            float a[8], b[8];
            float4 t0 = *(const float4*)&As[kk][rm0];
            float4 t1 = *(const float4*)&As[kk][rm0 + 4];
            float4 t2 = *(const float4*)&Ws[kk][rn0];
            float4 t3 = *(const float4*)&Ws[kk][rn0 + 4];
            a[0]=t0.x; a[1]=t0.y; a[2]=t0.z; a[3]=t0.w; a[4]=t1.x; a[5]=t1.y; a[6]=t1.z; a[7]=t1.w;
            b[0]=t2.x; b[1]=t2.y; b[2]=t2.z; b[3]=t2.w; b[4]=t3.x; b[5]=t3.y; b[6]=t3.z; b[7]=t3.w;
#pragma unroll
            for (int i = 0; i < 8; i++)
#pragma unroll
                for (int j = 0; j < 8; j++)
                    acc[i][j] = fmaf(a[i], b[j], acc[i][j]);
        }
        __syncthreads();
    }

    float br[8];
#pragma unroll
    for (int j = 0; j < 8; j++) br[j] = bias[col0 + rn0 + j];
    float ss = 0.f;
#pragma unroll
    for (int i = 0; i < 8; i++) {
#pragma unroll
        for (int j = 0; j < 8; j++) { acc[i][j] += br[j]; ss += acc[i][j] * acc[i][j]; }
        float* dst = C + (size_t)(row0 + rm0 + i) * 256 + col0 + rn0;
        *(float4*)dst       = make_float4(acc[i][0], acc[i][1], acc[i][2], acc[i][3]);
        *(float4*)(dst + 4) = make_float4(acc[i][4], acc[i][5], acc[i][6], acc[i][7]);
    }
    if (sqidx >= 0) {
#pragma unroll
        for (int o = 16; o > 0; o >>= 1) ss += __shfl_down_sync(0xffffffffu, ss, o);
        if ((t & 31) == 0) atomicAdd(&g_sumsq[sqidx], ss);
    }
}

// -------- degree: deg[col] += 1 --------
__global__ void deg_kernel(const int* __restrict__ ei) {
    int e = blockIdx.x * 256 + threadIdx.x;
    if (e < EE) atomicAdd(&g_deg[ei[EE + e]], 1.0f);
}

// -------- head-mean of v --------
__global__ void vmean_kernel() {
    int i = blockIdx.x * 256 + threadIdx.x;    // exactly NN*64 threads
    int n = i >> 6, d = i & 63;
    const float* vr = g_v + (size_t)n * 256 + d;
    g_vmean[i] = 0.25f * (vr[0] + vr[64] + vr[128] + vr[192]);
}

// -------- per (b,h): kv[k][v] = sum_m k*v; ksum; vsum (all unnormalized) --------
__global__ __launch_bounds__(256) void kv_kernel() {
    int bh = blockIdx.x;
    int b = bh >> 2, h = bh & 3;
    __shared__ float ks[8][64], vs[8][64];
    int t = threadIdx.x;
    int ty = t >> 4, tx = t & 15;
    float acc[4][4] = {};
    float s1 = 0.f, s2 = 0.f;
    const float* kb = g_k + (size_t)b * 512 * 256 + h * 64;
    const float* vb = g_v + (size_t)b * 512 * 256 + h * 64;

    for (int m0 = 0; m0 < 512; m0 += 8) {
#pragma unroll
        for (int j = 0; j < 2; j++) {
            int i = t + j * 256;
            int r = i >> 6, c = i & 63;
            ks[r][c] = kb[(size_t)(m0 + r) * 256 + c];
            vs[r][c] = vb[(size_t)(m0 + r) * 256 + c];
        }
        __syncthreads();
#pragma unroll
        for (int r = 0; r < 8; r++) {
            float kr[4], vr[4];
            float4 k4 = *(const float4*)&ks[r][ty * 4];
            float4 v4 = *(const float4*)&vs[r][tx * 4];
            kr[0]=k4.x; kr[1]=k4.y; kr[2]=k4.z; kr[3]=k4.w;
            vr[0]=v4.x; vr[1]=v4.y; vr[2]=v4.z; vr[3]=v4.w;
#pragma unroll
            for (int i = 0; i < 4; i++)
#pragma unroll
                for (int j = 0; j < 4; j++)
                    acc[i][j] = fmaf(kr[i], vr[j], acc[i][j]);
        }
        if (t < 64) {
#pragma unroll
            for (int r = 0; r < 8; r++) s1 += ks[r][t];
        } else if (t < 128) {
#pragma unroll
            for (int r = 0; r < 8; r++) s2 += vs[r][t - 64];
        }
        __syncthreads();
    }
    float* kvout = g_kv + (size_t)bh * 4096;
#pragma unroll
    for (int i = 0; i < 4; i++)
#pragma unroll
        for (int j = 0; j < 4; j++)
            kvout[(ty * 4 + i) * 64 + tx * 4 + j] = acc[i][j];
    if (t < 64) g_ksum[bh * 64 + t] = s1;
    else if (t < 128) g_vsum[bh * 64 + (t - 64)] = s2;
}

// -------- denom core: den[n][h] = q[n,h,:] . ksum[b,h,:]  (warp per node) --------
__global__ void den_kernel() {
    int gt = blockIdx.x * 256 + threadIdx.x;   // NN*32 threads
    int w = gt >> 5, lane = gt & 31;
    int b = w >> 9;
    const float* qr = g_q + (size_t)w * 256;
#pragma unroll
    for (int h = 0; h < 4; h++) {
        const float* ks = g_ksum + (b * 4 + h) * 64;
        float p = qr[h * 64 + lane] * ks[lane] + qr[h * 64 + 32 + lane] * ks[32 + lane];
#pragma unroll
        for (int o = 16; o > 0; o >>= 1) p += __shfl_down_sync(0xffffffffu, p, o);
        if (lane == 0) g_den[w * 4 + h] = p;
    }
}

// -------- numerator core as batched GEMM: P[m][d] = Q[m][k] @ KV[k][d], per (b,h), 64-row chunks --------
__global__ __launch_bounds__(256) void pn_kernel() {
    int bh = blockIdx.x, chunk = blockIdx.y;
    int b = bh >> 2, h = bh & 3;
    __shared__ float Qs[64][68];        // [k][m], padded
    __shared__ float KVs[64 * 64];      // [k][d]
    int t = threadIdx.x;
    const float* qb = g_q + (size_t)(b * 512 + chunk * 64) * 256 + h * 64;
    int la_m = t >> 2, la_k0 = (t & 3) * 4;
#pragma unroll
    for (int j = 0; j < 4; j++) {
        int kk = la_k0 + j * 16;
        float4 v4 = *(const float4*)(qb + (size_t)la_m * 256 + kk);
        Qs[kk + 0][la_m] = v4.x; Qs[kk + 1][la_m] = v4.y;
        Qs[kk + 2][la_m] = v4.z; Qs[kk + 3][la_m] = v4.w;
    }
    const float* kvb = g_kv + (size_t)bh * 4096;
#pragma unroll
    for (int j = 0; j < 4; j++)
        *(float4*)&KVs[(t + j * 256) * 4] = *(const float4*)(kvb + (t + j * 256) * 4);
    __syncthreads();

    int rm0 = (t >> 4) * 4, cn0 = (t & 15) * 4;
    float acc[4][4] = {};
#pragma unroll
    for (int k = 0; k < 64; k++) {
        float a[4], bb[4];
        float4 t0 = *(const float4*)&Qs[k][rm0];
        float4 t1 = *(const float4*)&KVs[k * 64 + cn0];
        a[0]=t0.x; a[1]=t0.y; a[2]=t0.z; a[3]=t0.w;
        bb[0]=t1.x; bb[1]=t1.y; bb[2]=t1.z; bb[3]=t1.w;
#pragma unroll
        for (int i = 0; i < 4; i++)
#pragma unroll
            for (int j = 0; j < 4; j++)
                acc[i][j] = fmaf(a[i], bb[j], acc[i][j]);
    }
#pragma unroll
    for (int i = 0; i < 4; i++) {
        int n = b * 512 + chunk * 64 + rm0 + i;
        *(float4*)(g_pn + ((size_t)n * 4 + h) * 64 + cn0) =
            make_float4(acc[i][0], acc[i][1], acc[i][2], acc[i][3]);
    }
}

// -------- combine: out[n][d] = 0.25 * sum_h (s*P + vsum) / (n_nodes + s*den) --------
__global__ void combine_kernel(const int* __restrict__ nnodes, float* __restrict__ out) {
    int i = blockIdx.x * 256 + threadIdx.x;    // exactly NN*64 threads
    int n = i >> 6, d = i & 63;
    int b = n >> 9;
    float s = rsqrtf(g_sumsq[0]) * rsqrtf(g_sumsq[1]);
    float nnv = (float)nnodes[b];
    float o = 0.f;
#pragma unroll
    for (int h = 0; h < 4; h++) {
        float num = fmaf(s, g_pn[((size_t)n * 4 + h) * 64 + d], g_vsum[(b * 4 + h) * 64 + d]);
        float den = fmaf(s, g_den[n * 4 + h], nnv);
        o += num / den;
    }
    out[i] = 0.25f * o;
}

// -------- GCN scatter on head-meaned v: out[col] += coeff * vmean[row] --------
__global__ void gcn_kernel(const int* __restrict__ ei, const float* __restrict__ ew,
                           float* __restrict__ out) {
    int gid = blockIdx.x * 256 + threadIdx.x;  // EE*16 threads, 16 per edge
    int e = gid >> 4, li = gid & 15;
    int row = ei[e];
    int col = ei[EE + e];
    float p = g_deg[col] * g_deg[row];
    float coeff = (p > 0.f) ? ew[e] * rsqrtf(p) : 0.f;   // nan_to_num: deg[row]==0 -> 0
    float4 vv = *(const float4*)(g_vmean + (size_t)row * 64 + li * 4);
    float* dst = out + (size_t)col * 64 + li * 4;
    asm volatile("red.global.add.v4.f32 [%0], {%1,%2,%3,%4};"
                 :: "l"(dst), "f"(coeff * vv.x), "f"(coeff * vv.y),
                    "f"(coeff * vv.z), "f"(coeff * vv.w)
                 : "memory");
}

extern "C" void kernel_launch(void* const* d_in, const int* in_sizes, int n_in,
                              void* d_out, int out_size) {
    const float* Xq = (const float*)d_in[0];
    const float* Xs = (const float*)d_in[1];
    const float* ew = (const float*)d_in[2];
    const float* Wq = (const float*)d_in[3];
    const float* bq = (const float*)d_in[4];
    const float* Wk = (const float*)d_in[5];
    const float* bk = (const float*)d_in[6];
    const float* Wv = (const float*)d_in[7];
    const float* bv = (const float*)d_in[8];
    const int*   nn = (const int*)d_in[9];
    const int*   ei = (const int*)d_in[10];
    float* out = (float*)d_out;

    init_kernel<<<128, 256>>>();
    proj_kernel<<<dim3(2, 256), 256>>>(Xq, Wq, bq, 0, 0);   // q + sumsq_q
    proj_kernel<<<dim3(2, 256), 256>>>(Xs, Wk, bk, 1, 1);   // k + sumsq_k
    proj_kernel<<<dim3(2, 256), 256>>>(Xs, Wv, bv, 2, -1);  // v
    deg_kernel<<<EE / 256, 256>>>(ei);
    vmean_kernel<<<(NN * 64) / 256, 256>>>();
    kv_kernel<<<BB * NH, 256>>>();
    den_kernel<<<(NN * 32) / 256, 256>>>();
    pn_kernel<<<dim3(BB * NH, 8), 256>>>();
    combine_kernel<<<(NN * 64) / 256, 256>>>(nn, out);
    gcn_kernel<<<(EE * 16) / 256, 256>>>(ei, ew, out);
}

// round 5
// speedup vs baseline: 1.7200x; 1.7200x over previous
#include <cuda_runtime.h>
#include <cuda_bf16.h>
#include <stdint.h>

#define NN 32768      // B*M nodes
#define NH 4
#define DD 64
#define BB 64
#define MM 512
#define EE 524288

// ================= device scratch =================
static __device__ float g_q[NN * 256];
static __device__ float g_k[NN * 256];
static __device__ float g_v[NN * 256];
static __device__ float g_vmean[NN * DD];
static __device__ float g_pn[NN * NH * DD];
static __device__ float g_kv[BB * NH * DD * DD];
static __device__ float g_ksum[BB * NH * DD];
static __device__ float g_vsum[BB * NH * DD];
static __device__ float g_den[NN * NH];
static __device__ float g_deg[NN];
static __device__ float g_sumsq[2];
static __device__ __align__(16) __nv_bfloat16 g_wth[3 * 256 * 256];  // [w][n][k] = W[k][n] hi
static __device__ __align__(16) __nv_bfloat16 g_wtl[3 * 256 * 256];  // lo residual

// ================= init =================
__global__ void init_kernel() {
    int i = blockIdx.x * 256 + threadIdx.x;
    if (i < NN) g_deg[i] = 0.f;
    if (i < 2) g_sumsq[i] = 0.f;
}

// ================= W transpose + bf16 hi/lo split =================
__global__ void wconv_kernel(const float* __restrict__ Wq, const float* __restrict__ Wk,
                             const float* __restrict__ Wv) {
    int w = blockIdx.y, n = blockIdx.x, k = threadIdx.x;
    const float* W = (w == 0) ? Wq : ((w == 1) ? Wk : Wv);
    float x = W[k * 256 + n];
    __nv_bfloat16 h = __float2bfloat16_rn(x);
    __nv_bfloat16 l = __float2bfloat16_rn(x - __bfloat162float(h));
    g_wth[(w * 256 + n) * 256 + k] = h;
    g_wtl[(w * 256 + n) * 256 + k] = l;
}

// ================= mma.sync helpers (arch-generic PTX, works on sm_103 base) =====
__device__ __forceinline__ uint32_t smem_u32(const void* p) {
    uint32_t a;
    asm("{ .reg .u64 t; cvta.to.shared.u64 t, %1; cvt.u32.u64 %0, t; }" : "=r"(a) : "l"(p));
    return a;
}
__device__ __forceinline__ void ldmx4(uint32_t* r, uint32_t addr) {
    asm volatile("ldmatrix.sync.aligned.m8n8.x4.shared.b16 {%0,%1,%2,%3}, [%4];"
                 : "=r"(r[0]), "=r"(r[1]), "=r"(r[2]), "=r"(r[3]) : "r"(addr));
}
__device__ __forceinline__ void mma16816(float* d, const uint32_t* a, const uint32_t* b) {
    asm volatile(
        "mma.sync.aligned.m16n8k16.row.col.f32.bf16.bf16.f32 "
        "{%0,%1,%2,%3}, {%4,%5,%6,%7}, {%8,%9}, {%0,%1,%2,%3};"
        : "+f"(d[0]), "+f"(d[1]), "+f"(d[2]), "+f"(d[3])
        : "r"(a[0]), "r"(a[1]), "r"(a[2]), "r"(a[3]), "r"(b[0]), "r"(b[1]));
}

// ================= projection GEMM via tensor cores (bf16x3 split) =================
// grid = (2, 256, 3): x = col tile (128), y = row tile (128), z = which GEMM.
// CTA tile 128x128, BK=32, 8 warps (2x4), warp tile 64x32 via m16n8k16.
// SMEM rows padded to 40 bf16 (80B) -> conflict-free ldmatrix.
#define SROW 40
__global__ __launch_bounds__(256, 2) void proj_mma_kernel(
    const float* __restrict__ Xq, const float* __restrict__ Xs,
    const float* __restrict__ bq, const float* __restrict__ bk,
    const float* __restrict__ bv)
{
    __shared__ __nv_bfloat16 Ah[128 * SROW], Al[128 * SROW];
    __shared__ __nv_bfloat16 Bh[128 * SROW], Bl[128 * SROW];

    const int t = threadIdx.x, lane = t & 31, wid = t >> 5;
    const int wm = wid >> 2, wn = wid & 3;          // 2 x 4 warp grid
    const int y = blockIdx.z;
    const float* A    = (y == 0) ? Xq : Xs;
    const float* bias = (y == 0) ? bq : ((y == 1) ? bk : bv);
    float* C          = (y == 0) ? g_q : ((y == 1) ? g_k : g_v);
    const int sqidx   = (y == 2) ? -1 : y;
    const int row0 = blockIdx.y * 128;
    const int col0 = blockIdx.x * 128;

    const __nv_bfloat16* Wth = g_wth + y * 65536;
    const __nv_bfloat16* Wtl = g_wtl + y * 65536;

    const uint32_t ah_b = smem_u32(Ah), al_b = smem_u32(Al);
    const uint32_t bh_b = smem_u32(Bh), bl_b = smem_u32(Bl);

    // ldmatrix lane addressing (byte offsets into padded [128][SROW] bf16 tile)
    // A fragment (16x16): rows lane&15, k-half (lane>>4)*8
    const uint32_t a_lrow = lane & 15, a_lcol = (lane >> 4) * 8;
    // B x4 (covers k0..31 for 8 n-rows): n-row lane&7, k-off (lane>>3)*8
    const uint32_t b_lrow = lane & 7, b_lcol = (lane >> 3) * 8;

    float acc[4][4][4];
#pragma unroll
    for (int i = 0; i < 4; i++)
#pragma unroll
        for (int j = 0; j < 4; j++)
#pragma unroll
            for (int r = 0; r < 4; r++) acc[i][j][r] = 0.f;

    const int ar = t >> 1, ac = (t & 1);       // A loader: 2 threads/row
    const int br2 = t >> 1, bq2 = t & 1;       // B loader

    for (int kt = 0; kt < 8; kt++) {
        const int k0 = kt * 32;
        __syncthreads();
        // ---- A chunk: fp32 -> bf16 hi/lo ----
#pragma unroll
        for (int i = 0; i < 4; i++) {
            int cf = ac * 4 + i;               // float4 index 0..7
            float4 a4 = *(const float4*)(A + (size_t)(row0 + ar) * 256 + k0 + cf * 4);
            __nv_bfloat16 h0 = __float2bfloat16_rn(a4.x), h1 = __float2bfloat16_rn(a4.y);
            __nv_bfloat16 h2 = __float2bfloat16_rn(a4.z), h3 = __float2bfloat16_rn(a4.w);
            __nv_bfloat16 l0 = __float2bfloat16_rn(a4.x - __bfloat162float(h0));
            __nv_bfloat16 l1 = __float2bfloat16_rn(a4.y - __bfloat162float(h1));
            __nv_bfloat16 l2 = __float2bfloat16_rn(a4.z - __bfloat162float(h2));
            __nv_bfloat16 l3 = __float2bfloat16_rn(a4.w - __bfloat162float(h3));
            __nv_bfloat162 ph0, ph1, pl0, pl1;
            ph0.x = h0; ph0.y = h1; ph1.x = h2; ph1.y = h3;
            pl0.x = l0; pl0.y = l1; pl1.x = l2; pl1.y = l3;
            int o = ar * SROW + cf * 4;
            *(uint2*)&Ah[o] = make_uint2(*(uint32_t*)&ph0, *(uint32_t*)&ph1);
            *(uint2*)&Al[o] = make_uint2(*(uint32_t*)&pl0, *(uint32_t*)&pl1);
        }
        // ---- B chunk (pre-split bf16 W^T rows) ----
#pragma unroll
        for (int j = 0; j < 2; j++) {
            int u = bq2 * 2 + j;               // uint4 index 0..3 (8 bf16 each)
            const char* srch = (const char*)(Wth + (size_t)(col0 + br2) * 256 + k0) + u * 16;
            const char* srcl = (const char*)(Wtl + (size_t)(col0 + br2) * 256 + k0) + u * 16;
            int o = br2 * SROW + u * 8;
            *(uint4*)&Bh[o] = *(const uint4*)srch;
            *(uint4*)&Bl[o] = *(const uint4*)srcl;
        }
        __syncthreads();

        // ---- preload B fragments (both k-halves) ----
        uint32_t bhf[4][4], blf[4][4];
#pragma unroll
        for (int nf = 0; nf < 4; nf++) {
            uint32_t n = wn * 32 + nf * 8 + b_lrow;
            uint32_t off = (n * SROW + b_lcol) * 2;
            ldmx4(bhf[nf], bh_b + off);
            ldmx4(blf[nf], bl_b + off);
        }
        // ---- mma ----
#pragma unroll
        for (int kf = 0; kf < 2; kf++) {
#pragma unroll
            for (int mf = 0; mf < 4; mf++) {
                uint32_t row = wm * 64 + mf * 16 + a_lrow;
                uint32_t off = (row * SROW + kf * 16 + a_lcol) * 2;
                uint32_t ahf[4], alf[4];
                ldmx4(ahf, ah_b + off);
                ldmx4(alf, al_b + off);
#pragma unroll
                for (int nf = 0; nf < 4; nf++) {
                    mma16816(acc[mf][nf], ahf, &bhf[nf][kf * 2]);
                    mma16816(acc[mf][nf], ahf, &blf[nf][kf * 2]);
                    mma16816(acc[mf][nf], alf, &bhf[nf][kf * 2]);
                }
            }
        }
    }

    // ---- epilogue: bias + store + global sumsq ----
    float ss = 0.f;
    const int rql = lane >> 2, cql = (lane & 3) * 2;
#pragma unroll
    for (int mf = 0; mf < 4; mf++) {
        int r0 = row0 + wm * 64 + mf * 16 + rql;
#pragma unroll
        for (int nf = 0; nf < 4; nf++) {
            int c = col0 + wn * 32 + nf * 8 + cql;
            float b0 = bias[c], b1 = bias[c + 1];
            float v0 = acc[mf][nf][0] + b0, v1 = acc[mf][nf][1] + b1;
            float v2 = acc[mf][nf][2] + b0, v3 = acc[mf][nf][3] + b1;
            ss += v0 * v0 + v1 * v1 + v2 * v2 + v3 * v3;
            *(float2*)(C + (size_t)r0 * 256 + c)       = make_float2(v0, v1);
            *(float2*)(C + (size_t)(r0 + 8) * 256 + c) = make_float2(v2, v3);
        }
    }
    if (sqidx >= 0) {
#pragma unroll
        for (int o = 16; o > 0; o >>= 1) ss += __shfl_down_sync(0xffffffffu, ss, o);
        if (lane == 0) atomicAdd(&g_sumsq[sqidx], ss);
    }
}

// ================= degree =================
__global__ void deg_kernel(const int* __restrict__ ei) {
    int e = blockIdx.x * 256 + threadIdx.x;
    if (e < EE) atomicAdd(&g_deg[ei[EE + e]], 1.0f);
}

// ================= head-mean of v =================
__global__ void vmean_kernel() {
    int i = blockIdx.x * 256 + threadIdx.x;
    int n = i >> 6, d = i & 63;
    const float* vr = g_v + (size_t)n * 256 + d;
    g_vmean[i] = 0.25f * (vr[0] + vr[64] + vr[128] + vr[192]);
}

// ================= per (b,h): kv, ksum, vsum =================
__global__ __launch_bounds__(256) void kv_kernel() {
    int bh = blockIdx.x;
    int b = bh >> 2, h = bh & 3;
    __shared__ float ks[8][64], vs[8][64];
    int t = threadIdx.x;
    int ty = t >> 4, tx = t & 15;
    float acc[4][4] = {};
    float s1 = 0.f, s2 = 0.f;
    const float* kb = g_k + (size_t)b * 512 * 256 + h * 64;
    const float* vb = g_v + (size_t)b * 512 * 256 + h * 64;

    for (int m0 = 0; m0 < 512; m0 += 8) {
#pragma unroll
        for (int j = 0; j < 2; j++) {
            int i = t + j * 256;
            int r = i >> 6, c2 = i & 63;
            ks[r][c2] = kb[(size_t)(m0 + r) * 256 + c2];
            vs[r][c2] = vb[(size_t)(m0 + r) * 256 + c2];
        }
        __syncthreads();
#pragma unroll
        for (int r = 0; r < 8; r++) {
            float kr[4], vr[4];
            float4 k4 = *(const float4*)&ks[r][ty * 4];
            float4 v4 = *(const float4*)&vs[r][tx * 4];
            kr[0]=k4.x; kr[1]=k4.y; kr[2]=k4.z; kr[3]=k4.w;
            vr[0]=v4.x; vr[1]=v4.y; vr[2]=v4.z; vr[3]=v4.w;
#pragma unroll
            for (int i = 0; i < 4; i++)
#pragma unroll
                for (int j = 0; j < 4; j++)
                    acc[i][j] = fmaf(kr[i], vr[j], acc[i][j]);
        }
        if (t < 64) {
#pragma unroll
            for (int r = 0; r < 8; r++) s1 += ks[r][t];
        } else if (t < 128) {
#pragma unroll
            for (int r = 0; r < 8; r++) s2 += vs[r][t - 64];
        }
        __syncthreads();
    }
    float* kvout = g_kv + (size_t)bh * 4096;
#pragma unroll
    for (int i = 0; i < 4; i++)
#pragma unroll
        for (int j = 0; j < 4; j++)
            kvout[(ty * 4 + i) * 64 + tx * 4 + j] = acc[i][j];
    if (t < 64) g_ksum[bh * 64 + t] = s1;
    else if (t < 128) g_vsum[bh * 64 + (t - 64)] = s2;
}

// ================= denom =================
__global__ void den_kernel() {
    int gt = blockIdx.x * 256 + threadIdx.x;
    int w = gt >> 5, lane = gt & 31;
    int b = w >> 9;
    const float* qr = g_q + (size_t)w * 256;
#pragma unroll
    for (int h = 0; h < 4; h++) {
        const float* ks = g_ksum + (b * 4 + h) * 64;
        float p = qr[h * 64 + lane] * ks[lane] + qr[h * 64 + 32 + lane] * ks[32 + lane];
#pragma unroll
        for (int o = 16; o > 0; o >>= 1) p += __shfl_down_sync(0xffffffffu, p, o);
        if (lane == 0) g_den[w * 4 + h] = p;
    }
}

// ================= numerator batched GEMM =================
__global__ __launch_bounds__(256) void pn_kernel() {
    int bh = blockIdx.x, chunk = blockIdx.y;
    int b = bh >> 2, h = bh & 3;
    __shared__ float Qs[64][68];
    __shared__ float KVs[64 * 64];
    int t = threadIdx.x;
    const float* qb = g_q + (size_t)(b * 512 + chunk * 64) * 256 + h * 64;
    int la_m = t >> 2, la_k0 = (t & 3) * 4;
#pragma unroll
    for (int j = 0; j < 4; j++) {
        int kk = la_k0 + j * 16;
        float4 v4 = *(const float4*)(qb + (size_t)la_m * 256 + kk);
        Qs[kk + 0][la_m] = v4.x; Qs[kk + 1][la_m] = v4.y;
        Qs[kk + 2][la_m] = v4.z; Qs[kk + 3][la_m] = v4.w;
    }
    const float* kvb = g_kv + (size_t)bh * 4096;
#pragma unroll
    for (int j = 0; j < 4; j++)
        *(float4*)&KVs[(t + j * 256) * 4] = *(const float4*)(kvb + (t + j * 256) * 4);
    __syncthreads();

    int rm0 = (t >> 4) * 4, cn0 = (t & 15) * 4;
    float acc[4][4] = {};
#pragma unroll
    for (int k = 0; k < 64; k++) {
        float a[4], bb[4];
        float4 t0 = *(const float4*)&Qs[k][rm0];
        float4 t1 = *(const float4*)&KVs[k * 64 + cn0];
        a[0]=t0.x; a[1]=t0.y; a[2]=t0.z; a[3]=t0.w;
        bb[0]=t1.x; bb[1]=t1.y; bb[2]=t1.z; bb[3]=t1.w;
#pragma unroll
        for (int i = 0; i < 4; i++)
#pragma unroll
            for (int j = 0; j < 4; j++)
                acc[i][j] = fmaf(a[i], bb[j], acc[i][j]);
    }
#pragma unroll
    for (int i = 0; i < 4; i++) {
        int n = b * 512 + chunk * 64 + rm0 + i;
        *(float4*)(g_pn + ((size_t)n * 4 + h) * 64 + cn0) =
            make_float4(acc[i][0], acc[i][1], acc[i][2], acc[i][3]);
    }
}

// ================= combine =================
__global__ void combine_kernel(const int* __restrict__ nnodes, float* __restrict__ out) {
    int i = blockIdx.x * 256 + threadIdx.x;
    int n = i >> 6, d = i & 63;
    int b = n >> 9;
    float s = rsqrtf(g_sumsq[0]) * rsqrtf(g_sumsq[1]);
    float nnv = (float)nnodes[b];
    float o = 0.f;
#pragma unroll
    for (int h = 0; h < 4; h++) {
        float num = fmaf(s, g_pn[((size_t)n * 4 + h) * 64 + d], g_vsum[(b * 4 + h) * 64 + d]);
        float den = fmaf(s, g_den[n * 4 + h], nnv);
        o += num / den;
    }
    out[i] = 0.25f * o;
}

// ================= GCN scatter =================
__global__ void gcn_kernel(const int* __restrict__ ei, const float* __restrict__ ew,
                           float* __restrict__ out) {
    int gid = blockIdx.x * 256 + threadIdx.x;
    int e = gid >> 4, li = gid & 15;
    int row = ei[e];
    int col = ei[EE + e];
    float p = g_deg[col] * g_deg[row];
    float coeff = (p > 0.f) ? ew[e] * rsqrtf(p) : 0.f;
    float4 vv = *(const float4*)(g_vmean + (size_t)row * 64 + li * 4);
    float* dst = out + (size_t)col * 64 + li * 4;
    asm volatile("red.global.add.v4.f32 [%0], {%1,%2,%3,%4};"
                 :: "l"(dst), "f"(coeff * vv.x), "f"(coeff * vv.y),
                    "f"(coeff * vv.z), "f"(coeff * vv.w)
                 : "memory");
}

extern "C" void kernel_launch(void* const* d_in, const int* in_sizes, int n_in,
                              void* d_out, int out_size) {
    const float* Xq = (const float*)d_in[0];
    const float* Xs = (const float*)d_in[1];
    const float* ew = (const float*)d_in[2];
    const float* Wq = (const float*)d_in[3];
    const float* bq = (const float*)d_in[4];
    const float* Wk = (const float*)d_in[5];
    const float* bk = (const float*)d_in[6];
    const float* Wv = (const float*)d_in[7];
    const float* bv = (const float*)d_in[8];
    const int*   nn = (const int*)d_in[9];
    const int*   ei = (const int*)d_in[10];
    float* out = (float*)d_out;

    init_kernel<<<128, 256>>>();
    wconv_kernel<<<dim3(256, 3), 256>>>(Wq, Wk, Wv);
    proj_mma_kernel<<<dim3(2, 256, 3), 256>>>(Xq, Xs, bq, bk, bv);
    deg_kernel<<<EE / 256, 256>>>(ei);
    vmean_kernel<<<(NN * 64) / 256, 256>>>();
    kv_kernel<<<BB * NH, 256>>>();
    den_kernel<<<(NN * 32) / 256, 256>>>();
    pn_kernel<<<dim3(BB * NH, 8), 256>>>();
    combine_kernel<<<(NN * 64) / 256, 256>>>(nn, out);
    gcn_kernel<<<(EE * 16) / 256, 256>>>(ei, ew, out);
}